// round 1
// baseline (speedup 1.0000x reference)
#include <cuda_runtime.h>

#define B_    4
#define C_    64
#define T_    80
#define H_    36
#define W_    64
#define S_    (H_*W_)        // 2304
#define N_    128
#define NT_   10
#define TOUT_ (T_ - NT_ + 1) // 71
#define F_    (B_*T_)        // 320
#define KT    16

// scratch (device globals; no allocation in kernel_launch)
__device__ float g_gx[W_*N_];
__device__ float g_gy[H_*N_];
__device__ float g_invZ[N_];
__device__ float g_ws[S_*N_];     // [s][n], s = y*W + x
__device__ float g_R[F_*N_];      // [f][n], f = b*T + t

// ---------------------------------------------------------------------------
// 1) per-target Gaussian factors gx[x,n], gy[y,n] and normalizer 1/(0.1+Z)
// ---------------------------------------------------------------------------
__global__ void setup_kernel(const float* __restrict__ wx, const float* __restrict__ wy,
                             const float* __restrict__ wsx, const float* __restrict__ wsy) {
    int n = threadIdx.x;  // 128 threads
    float rx = fmaxf(wsx[n], 0.0f);
    float ry = fmaxf(wsy[n], 0.0f);
    float inv2sx = 1.0f / (2.0f * (0.1f + rx * rx));
    float inv2sy = 1.0f / (2.0f * (0.1f + ry * ry));
    float cx = wx[n], cy = wy[n];

    float sgx = 0.0f;
    for (int xp = 0; xp < W_; xp++) {
        float xv = ((float)xp - 0.5f * W_ + 0.5f) / (float)W_;
        float d = xv - cx;
        float g = expf(-d * d * inv2sx);
        g_gx[xp * N_ + n] = g;
        sgx += g;
    }
    float sgy = 0.0f;
    for (int yp = 0; yp < H_; yp++) {
        float yv = ((float)yp - 0.5f * H_ + 0.5f) / (float)H_;
        float d = yv - cy;
        float g = expf(-d * d * inv2sy);
        g_gy[yp * N_ + n] = g;
        sgy += g;
    }
    g_invZ[n] = 1.0f / (0.1f + sgx * sgy);
}

// ---------------------------------------------------------------------------
// 2) materialize ws[s][n] (1.18 MB, L2-resident for the GEMM)
// ---------------------------------------------------------------------------
__global__ void wsfill_kernel() {
    int idx = blockIdx.x * blockDim.x + threadIdx.x;
    if (idx >= S_ * N_) return;
    int n = idx & (N_ - 1);
    int s = idx >> 7;
    int yp = s / W_;
    int xp = s - yp * W_;
    g_ws[idx] = g_gy[yp * N_ + n] * g_gx[xp * N_ + n] * g_invZ[n];
}

// ---------------------------------------------------------------------------
// 3) main GEMM: one block per frame f.
//    T1[c,n] = sum_s x[f,c,s] * ws[s,n]   (64 x 128 x 2304)
//    R[f,n]  = sum_c wc[c,n] * T1[c,n]
//    256 threads; each thread owns an 8(c) x 4(n) register tile.
// ---------------------------------------------------------------------------
__global__ void __launch_bounds__(256, 2)
pool_gemm_kernel(const float* __restrict__ x, const float* __restrict__ wc) {
    __shared__ float As[KT][68];    // [k][c], padded
    __shared__ float Bs[KT][N_];    // [k][n]
    __shared__ float red[8][N_];

    const int f  = blockIdx.x;
    const int bb = f / T_;
    const int tt = f - bb * T_;
    const int tid = threadIdx.x;
    const int tx = tid & 31;        // n-group: n = tx*4 + j
    const int ty = tid >> 5;        // c-group: c = ty*8 + i

    // A loader mapping: thread -> (c = tid/4, k offset = (tid%4)*4), float4
    const int lc = tid >> 2;
    const int lk = (tid & 3) * 4;
    const float* Arow = x + ((size_t)(bb * C_ + lc) * T_ + tt) * (size_t)S_ + lk;

    // B loader mapping: rows ty and ty+8, columns tx*4..tx*4+3
    const float* Bptr0 = &g_ws[(size_t)ty * N_ + tx * 4];
    const float* Bptr1 = &g_ws[(size_t)(ty + 8) * N_ + tx * 4];

    float acc[8][4];
#pragma unroll
    for (int i = 0; i < 8; i++)
#pragma unroll
        for (int j = 0; j < 4; j++) acc[i][j] = 0.0f;

    for (int k0 = 0; k0 < S_; k0 += KT) {
        float4 av  = *reinterpret_cast<const float4*>(Arow + k0);
        float4 bv0 = *reinterpret_cast<const float4*>(Bptr0 + (size_t)k0 * N_);
        float4 bv1 = *reinterpret_cast<const float4*>(Bptr1 + (size_t)k0 * N_);

        __syncthreads();
        As[lk + 0][lc] = av.x;
        As[lk + 1][lc] = av.y;
        As[lk + 2][lc] = av.z;
        As[lk + 3][lc] = av.w;
        *reinterpret_cast<float4*>(&Bs[ty][tx * 4])     = bv0;
        *reinterpret_cast<float4*>(&Bs[ty + 8][tx * 4]) = bv1;
        __syncthreads();

#pragma unroll
        for (int k = 0; k < KT; k++) {
            float4 a0 = *reinterpret_cast<const float4*>(&As[k][ty * 8]);
            float4 a1 = *reinterpret_cast<const float4*>(&As[k][ty * 8 + 4]);
            float4 b  = *reinterpret_cast<const float4*>(&Bs[k][tx * 4]);
            float a[8] = {a0.x, a0.y, a0.z, a0.w, a1.x, a1.y, a1.z, a1.w};
            float bb4[4] = {b.x, b.y, b.z, b.w};
#pragma unroll
            for (int i = 0; i < 8; i++)
#pragma unroll
                for (int j = 0; j < 4; j++) acc[i][j] += a[i] * bb4[j];
        }
    }

    // epilogue: fold in wc and reduce over c
    float part[4] = {0.0f, 0.0f, 0.0f, 0.0f};
#pragma unroll
    for (int i = 0; i < 8; i++) {
        int c = ty * 8 + i;
#pragma unroll
        for (int j = 0; j < 4; j++)
            part[j] += wc[c * N_ + tx * 4 + j] * acc[i][j];
    }
    __syncthreads();
#pragma unroll
    for (int j = 0; j < 4; j++) red[ty][tx * 4 + j] = part[j];
    __syncthreads();
    if (ty == 0) {
#pragma unroll
        for (int j = 0; j < 4; j++) {
            float s = 0.0f;
#pragma unroll
            for (int yy = 0; yy < 8; yy++) s += red[yy][tx * 4 + j];
            g_R[f * N_ + tx * 4 + j] = s;
        }
    }
}

// ---------------------------------------------------------------------------
// 4) grouped temporal conv (VALID, cross-correlation) + bias
//    out[b, n, t'] = wb[n] + sum_k R[b*T + t' + k, n] * wt[k, n]
// ---------------------------------------------------------------------------
__global__ void conv_kernel(const float* __restrict__ wt, const float* __restrict__ wb,
                            float* __restrict__ out) {
    int idx = blockIdx.x * blockDim.x + threadIdx.x;
    if (idx >= B_ * N_ * TOUT_) return;
    int tp = idx % TOUT_;
    int n  = (idx / TOUT_) % N_;
    int b  = idx / (TOUT_ * N_);
    float s = wb[n];
#pragma unroll
    for (int k = 0; k < NT_; k++)
        s += g_R[(b * T_ + tp + k) * N_ + n] * wt[k * N_ + n];
    out[idx] = s;
}

// ---------------------------------------------------------------------------
extern "C" void kernel_launch(void* const* d_in, const int* in_sizes, int n_in,
                              void* d_out, int out_size) {
    (void)in_sizes; (void)n_in; (void)out_size;
    const float* x   = (const float*)d_in[0];
    // d_in[1] = targets (all true) — unused
    const float* wc  = (const float*)d_in[2];
    const float* wx  = (const float*)d_in[3];
    const float* wy  = (const float*)d_in[4];
    const float* wsx = (const float*)d_in[5];
    const float* wsy = (const float*)d_in[6];
    const float* wt  = (const float*)d_in[7];
    const float* wb  = (const float*)d_in[8];
    float* out = (float*)d_out;

    setup_kernel<<<1, N_>>>(wx, wy, wsx, wsy);
    wsfill_kernel<<<(S_ * N_ + 255) / 256, 256>>>();
    pool_gemm_kernel<<<F_, 256>>>(x, wc);
    conv_kernel<<<(B_ * N_ * TOUT_ + 255) / 256, 256>>>(wt, wb, out);
}

// round 3
// speedup vs baseline: 2.4398x; 2.4398x over previous
#include <cuda_runtime.h>
#include <cuda_bf16.h>
#include <cstdint>

#define B_    4
#define C_    64
#define T_    80
#define H_    36
#define W_    64
#define S_    2304
#define N_    128
#define NT_   10
#define TOUT_ 71
#define F_    320
#define KC    64            // K elements per chunk
#define NCHUNK (S_/KC)      // 36

// ---------------- device scratch -------------------------------------------
__device__ float g_gx[W_*N_];
__device__ float g_gy[H_*N_];
__device__ float g_invZ[N_];
__device__ __align__(16) __nv_bfloat16 g_wsT[N_*S_];   // B matrix: [n][s] bf16
__device__ float g_Rt[B_*N_*T_];                        // [b][n][t]

// ---------------- helpers ----------------------------------------------------
__device__ __forceinline__ uint32_t smem_u32(const void* p) {
    uint32_t a;
    asm("{ .reg .u64 t; cvta.to.shared.u64 t, %1; cvt.u32.u64 %0, t; }" : "=r"(a) : "l"(p));
    return a;
}
__device__ __forceinline__ uint32_t pack_bf16(float lo, float hi) {
    uint32_t r;
    asm("cvt.rn.bf16x2.f32 %0, %1, %2;" : "=r"(r) : "f"(hi), "f"(lo));
    return r;
}
__device__ __forceinline__ void cp16(uint32_t dst, const void* src) {
    asm volatile("cp.async.cg.shared.global [%0], [%1], 16;" :: "r"(dst), "l"(src) : "memory");
}
#define CP_COMMIT() asm volatile("cp.async.commit_group;" ::: "memory")
#define CP_WAIT1()  asm volatile("cp.async.wait_group 1;" ::: "memory")

__device__ __forceinline__ void mma_bf16(float* d, const uint32_t* a, const uint32_t* b) {
    asm volatile("mma.sync.aligned.m16n8k16.row.col.f32.bf16.bf16.f32 "
        "{%0,%1,%2,%3}, {%4,%5,%6,%7}, {%8,%9}, {%0,%1,%2,%3};"
        : "+f"(d[0]), "+f"(d[1]), "+f"(d[2]), "+f"(d[3])
        : "r"(a[0]), "r"(a[1]), "r"(a[2]), "r"(a[3]), "r"(b[0]), "r"(b[1]));
}

// swizzled byte offsets (A: fp32 rows of 256B, 32B granules; B: bf16 rows of 128B, 16B granules)
__device__ __forceinline__ uint32_t aswz(int r, int g) { return (uint32_t)(r*256 + ((g ^ (r & 7)) << 5)); }
__device__ __forceinline__ uint32_t bswz(int n, int g) { return (uint32_t)(n*128 + ((g ^ (n & 7)) << 4)); }

// ---------------------------------------------------------------------------
// 1) Gaussian factors
// ---------------------------------------------------------------------------
__global__ void setup_kernel(const float* __restrict__ wx, const float* __restrict__ wy,
                             const float* __restrict__ wsx, const float* __restrict__ wsy) {
    int n = threadIdx.x;
    float rx = fmaxf(wsx[n], 0.0f), ry = fmaxf(wsy[n], 0.0f);
    float inv2sx = 1.0f / (2.0f * (0.1f + rx * rx));
    float inv2sy = 1.0f / (2.0f * (0.1f + ry * ry));
    float cx = wx[n], cy = wy[n];
    float sgx = 0.0f;
    for (int xp = 0; xp < W_; xp++) {
        float xv = ((float)xp - 0.5f * W_ + 0.5f) / (float)W_;
        float d = xv - cx; float g = expf(-d * d * inv2sx);
        g_gx[xp * N_ + n] = g; sgx += g;
    }
    float sgy = 0.0f;
    for (int yp = 0; yp < H_; yp++) {
        float yv = ((float)yp - 0.5f * H_ + 0.5f) / (float)H_;
        float d = yv - cy; float g = expf(-d * d * inv2sy);
        g_gy[yp * N_ + n] = g; sgy += g;
    }
    g_invZ[n] = 1.0f / (0.1f + sgx * sgy);
}

// ---------------------------------------------------------------------------
// 2) wsT[n][s] bf16
// ---------------------------------------------------------------------------
__global__ void wsfill_kernel() {
    int idx = blockIdx.x * blockDim.x + threadIdx.x;
    if (idx >= N_ * S_) return;
    int n = idx / S_;
    int s = idx - n * S_;
    int yp = s / W_;
    int xp = s - yp * W_;
    float v = g_gy[yp * N_ + n] * g_gx[xp * N_ + n] * g_invZ[n];
    g_wsT[idx] = __float2bfloat16(v);
}

// ---------------------------------------------------------------------------
// 3) HMMA GEMM: 128 rows=(f,c) x 128 n x K=2304 per CTA, 160 CTAs.
// ---------------------------------------------------------------------------
#define SM_A0   0
#define SM_A1   32768
#define SM_B0   65536
#define SM_B1   81920
#define SMEM_SZ 98304
#define T1_STRIDE 136

extern "C" __global__ void __launch_bounds__(256)
gemm_kernel(const float* __restrict__ x, const float* __restrict__ wc) {
    extern __shared__ __align__(16) char smem[];
    const uint32_t sb = smem_u32(smem);
    const int tid  = threadIdx.x;
    const int wid  = tid >> 5;
    const int lane = tid & 31;
    const int wm   = wid & 3;     // m block: rows wm*32..+31
    const int wn   = wid >> 2;    // n block: cols wn*64..+63

    // loader mapping: r/n = tid/2, h = tid&1 (half a row per thread)
    const int lr = tid >> 1;
    const int lh = tid & 1;
    const int gr = blockIdx.x * 128 + lr;
    const int lf = gr >> 6;                 // frame
    const int lc = gr & 63;                 // channel
    const int lbb = lf / T_;
    const int ltt = lf - lbb * T_;
    const float* asrc_base = x + ((size_t)((lbb * C_ + lc) * T_ + ltt)) * S_ + lh * 32;
    const __nv_bfloat16* bsrc_base = g_wsT + (size_t)lr * S_;

    const uint32_t abuf[2] = { sb + SM_A0, sb + SM_A1 };
    const uint32_t bbuf[2] = { sb + SM_B0, sb + SM_B1 };

    // ---- async load issue for one chunk ----
    auto issue = [&](int chunk, int p) {
        const float* as = asrc_base + (size_t)chunk * KC;
#pragma unroll
        for (int jj = 0; jj < 4; jj++) {
            int g = lh * 4 + jj;
            uint32_t d = abuf[p] + aswz(lr, g);
            cp16(d,      as + jj * 8);
            cp16(d + 16, as + jj * 8 + 4);
        }
        const __nv_bfloat16* bs = bsrc_base + (size_t)chunk * KC;
#pragma unroll
        for (int jj = 0; jj < 4; jj++) {
            int g = lh * 4 + jj;
            cp16(bbuf[p] + bswz(lr, g), bs + g * 8);
        }
    };

    float acc[2][8][4];
#pragma unroll
    for (int mt = 0; mt < 2; mt++)
#pragma unroll
        for (int j = 0; j < 8; j++)
#pragma unroll
            for (int q = 0; q < 4; q++) acc[mt][j][q] = 0.0f;

    issue(0, 0); CP_COMMIT();
    issue(1, 1); CP_COMMIT();

    const int lrow = lane >> 2;     // 0..7
    const int lq   = lane & 3;      // 0..3

    for (int i = 0; i < NCHUNK; i++) {
        const int p = i & 1;
        CP_WAIT1();
        __syncthreads();
        const uint32_t Ab = abuf[p], Bb = bbuf[p];
#pragma unroll
        for (int q = 0; q < 4; q++) {
            uint32_t afr[2][4];
#pragma unroll
            for (int mt = 0; mt < 2; mt++) {
                int r = wm * 32 + mt * 16 + lrow;
#pragma unroll
                for (int half = 0; half < 2; half++) {
#pragma unroll
                    for (int dr = 0; dr < 2; dr++) {
                        float2 v;
                        uint32_t ad = Ab + aswz(r + dr * 8, q * 2 + half) + lq * 8;
                        asm volatile("ld.shared.v2.f32 {%0,%1}, [%2];"
                                     : "=f"(v.x), "=f"(v.y) : "r"(ad));
                        afr[mt][half * 2 + dr] = pack_bf16(v.x, v.y);
                    }
                }
            }
            uint32_t bfr[8][2];
#pragma unroll
            for (int j = 0; j < 8; j++) {
                int n = wn * 64 + j * 8 + lrow;
#pragma unroll
                for (int half = 0; half < 2; half++) {
                    uint32_t bd = Bb + bswz(n, q * 2 + half) + lq * 4;
                    asm volatile("ld.shared.b32 %0, [%1];" : "=r"(bfr[j][half]) : "r"(bd));
                }
            }
#pragma unroll
            for (int mt = 0; mt < 2; mt++)
#pragma unroll
                for (int j = 0; j < 8; j++)
                    mma_bf16(acc[mt][j], afr[mt], bfr[j]);
        }
        __syncthreads();
        if (i + 2 < NCHUNK) issue(i + 2, p);
        CP_COMMIT();
    }

    // ---- epilogue: T1 -> SMEM, fold wc, reduce over c ----
    float* Tsm = (float*)smem;      // [128][T1_STRIDE]
#pragma unroll
    for (int mt = 0; mt < 2; mt++) {
#pragma unroll
        for (int j = 0; j < 8; j++) {
            int r0  = wm * 32 + mt * 16 + lrow;
            int col = wn * 64 + j * 8 + lq * 2;
            uint32_t a0 = sb + (uint32_t)((r0 * T1_STRIDE + col) * 4);
            uint32_t a1 = sb + (uint32_t)(((r0 + 8) * T1_STRIDE + col) * 4);
            asm volatile("st.shared.v2.f32 [%0], {%1,%2};"
                         :: "r"(a0), "f"(acc[mt][j][0]), "f"(acc[mt][j][1]));
            asm volatile("st.shared.v2.f32 [%0], {%1,%2};"
                         :: "r"(a1), "f"(acc[mt][j][2]), "f"(acc[mt][j][3]));
        }
    }
    __syncthreads();

    {
        int fl = tid >> 7;          // 0..1
        int n  = tid & 127;
        float s = 0.0f;
        const float* tp = Tsm + (size_t)fl * 64 * T1_STRIDE + n;
#pragma unroll 16
        for (int c2 = 0; c2 < 64; c2++)
            s += tp[c2 * T1_STRIDE] * __ldg(&wc[c2 * N_ + n]);
        int fg = blockIdx.x * 2 + fl;
        int b2 = fg / T_, t2 = fg - (fg / T_) * T_;
        g_Rt[(b2 * N_ + n) * T_ + t2] = s;
    }
}

// ---------------------------------------------------------------------------
// 4) temporal conv: one warp per (b, n) row
// ---------------------------------------------------------------------------
__global__ void conv_kernel(const float* __restrict__ wt, const float* __restrict__ wb,
                            float* __restrict__ out) {
    __shared__ float rr[8][80];
    __shared__ float wts[8][10];
    int wid = threadIdx.x >> 5, lane = threadIdx.x & 31;
    int row = blockIdx.x * 8 + wid;        // row = b*N + n
    int n = row & 127;
    const float* R = g_Rt + (size_t)row * T_;
    if (lane < 10) wts[wid][lane] = wt[lane * N_ + n];
    rr[wid][lane]      = R[lane];
    rr[wid][lane + 32] = R[lane + 32];
    if (lane < 16) rr[wid][lane + 64] = R[lane + 64];
    __syncwarp();
    float bias = wb[n];
    for (int t0 = lane; t0 < TOUT_; t0 += 32) {
        float s = bias;
#pragma unroll
        for (int k = 0; k < NT_; k++) s += rr[wid][t0 + k] * wts[wid][k];
        out[(size_t)row * TOUT_ + t0] = s;
    }
}

// ---------------------------------------------------------------------------
extern "C" void kernel_launch(void* const* d_in, const int* in_sizes, int n_in,
                              void* d_out, int out_size) {
    (void)in_sizes; (void)n_in; (void)out_size;
    const float* x   = (const float*)d_in[0];
    const float* wc  = (const float*)d_in[2];
    const float* wx  = (const float*)d_in[3];
    const float* wy  = (const float*)d_in[4];
    const float* wsx = (const float*)d_in[5];
    const float* wsy = (const float*)d_in[6];
    const float* wt  = (const float*)d_in[7];
    const float* wb  = (const float*)d_in[8];
    float* out = (float*)d_out;

    cudaFuncSetAttribute(gemm_kernel, cudaFuncAttributeMaxDynamicSharedMemorySize, SMEM_SZ);

    setup_kernel<<<1, N_>>>(wx, wy, wsx, wsy);
    wsfill_kernel<<<(N_ * S_ + 255) / 256, 256>>>();
    gemm_kernel<<<F_ / 2, 256, SMEM_SZ>>>(x, wc);
    conv_kernel<<<(B_ * N_) / 8, 256>>>(wt, wb, out);
}